// round 5
// baseline (speedup 1.0000x reference)
#include <cuda_runtime.h>
#include <cuda_bf16.h>
#include <cstdint>

#define DEV_INLINE __device__ __forceinline__

constexpr int Bb = 8;
constexpr int Nn = 4096;

// ---------------- static device scratch (no allocation) ----------------
__device__ float    g_h32[Bb * Nn * 64];          // h fp32 (8 MB)
__device__ unsigned g_hpk_hi[Bb * (Nn/2) * 64];   // h bf16, node-pair packed (4 MB)

// ============================================================================
// Kernel 1: h[b,n,j] = sum_{m,a} x[b,n,m,a]*W[m,p(j),a,w(j)]
// 256 threads: thread = (node pair, p). acc[2][16]; pair packing thread-local.
// ============================================================================
__global__ void __launch_bounds__(256)
spconv_h_kernel(const float* __restrict__ x, const float* __restrict__ wgt)
{
    __shared__ float ws[128 * 64];   // ws[ka*64 + j],  j = p*16 + w
    const int t = threadIdx.x;
    const int b = blockIdx.y;
    const int ng = t >> 2;                    // 0..63
    const int p  = t & 3;
    const int node0 = blockIdx.x * 128 + ng * 2;

    for (int idx = t; idx < 128 * 64; idx += 256) {
        int ka = idx >> 6, j = idx & 63;
        int m = ka >> 5, a = ka & 31, pp = j >> 4, w = j & 15;
        ws[idx] = wgt[(((m * 4 + pp) * 32 + a) << 4) + w];
    }
    __syncthreads();

    float acc[2][16];
#pragma unroll
    for (int nd = 0; nd < 2; nd++)
#pragma unroll
        for (int i = 0; i < 16; i++) acc[nd][i] = 0.f;

    const float* xr = x + (size_t)(b * Nn + node0) * 128;
#pragma unroll 1
    for (int ka4 = 0; ka4 < 32; ka4++) {
        float xa[2][4];
#pragma unroll
        for (int nd = 0; nd < 2; nd++) {
            float4 v = *(const float4*)(xr + nd * 128 + ka4 * 4);
            xa[nd][0] = v.x; xa[nd][1] = v.y; xa[nd][2] = v.z; xa[nd][3] = v.w;
        }
#pragma unroll
        for (int i = 0; i < 4; i++) {
            const float4* wr = (const float4*)&ws[(ka4 * 4 + i) * 64 + p * 16];
            float4 w0 = wr[0], w1 = wr[1], w2 = wr[2], w3 = wr[3];
#pragma unroll
            for (int nd = 0; nd < 2; nd++) {
                const float xs = xa[nd][i];
                acc[nd][ 0] = fmaf(xs, w0.x, acc[nd][ 0]);
                acc[nd][ 1] = fmaf(xs, w0.y, acc[nd][ 1]);
                acc[nd][ 2] = fmaf(xs, w0.z, acc[nd][ 2]);
                acc[nd][ 3] = fmaf(xs, w0.w, acc[nd][ 3]);
                acc[nd][ 4] = fmaf(xs, w1.x, acc[nd][ 4]);
                acc[nd][ 5] = fmaf(xs, w1.y, acc[nd][ 5]);
                acc[nd][ 6] = fmaf(xs, w1.z, acc[nd][ 6]);
                acc[nd][ 7] = fmaf(xs, w1.w, acc[nd][ 7]);
                acc[nd][ 8] = fmaf(xs, w2.x, acc[nd][ 8]);
                acc[nd][ 9] = fmaf(xs, w2.y, acc[nd][ 9]);
                acc[nd][10] = fmaf(xs, w2.z, acc[nd][10]);
                acc[nd][11] = fmaf(xs, w2.w, acc[nd][11]);
                acc[nd][12] = fmaf(xs, w3.x, acc[nd][12]);
                acc[nd][13] = fmaf(xs, w3.y, acc[nd][13]);
                acc[nd][14] = fmaf(xs, w3.z, acc[nd][14]);
                acc[nd][15] = fmaf(xs, w3.w, acc[nd][15]);
            }
        }
    }

    // fp32 h for epilogue
#pragma unroll
    for (int nd = 0; nd < 2; nd++) {
        float* hp = g_h32 + (size_t)(b * Nn + node0 + nd) * 64 + p * 16;
#pragma unroll
        for (int w4 = 0; w4 < 4; w4++)
            *(float4*)(hp + w4 * 4) = make_float4(acc[nd][w4*4+0], acc[nd][w4*4+1],
                                                  acc[nd][w4*4+2], acc[nd][w4*4+3]);
    }

    // node-pair packed bf16 (pair is thread-local)
    {
        const size_t pb = ((size_t)(b * 2048 + (node0 >> 1))) * 64 + p * 16;
        unsigned hi[16];
#pragma unroll
        for (int w = 0; w < 16; w++) {
            __nv_bfloat162 t2 = __floats2bfloat162_rn(acc[0][w], acc[1][w]);
            hi[w] = *reinterpret_cast<unsigned*>(&t2);
        }
#pragma unroll
        for (int w4 = 0; w4 < 4; w4++)
            *(uint4*)(g_hpk_hi + pb + w4 * 4) =
                make_uint4(hi[w4*4], hi[w4*4+1], hi[w4*4+2], hi[w4*4+3]);
    }
}

// ============================================================================
// Kernel 2: per-batch C = adj @ h, fused rowsum/normalize/self-loop/relu/bias.
// 1-pass bf16. BM=64 BN=64 BK=32, 256 thr, 8 warps (4 row x 2 col), warp tile
// 16x32. Double-buffered smem, one barrier per k-tile, 4 CTAs/SM.
// ============================================================================
constexpr int A_STR = 20;                 // u32 per A row (16 kpairs + 4 pad)
constexpr int B_STR = 72;                 // u32 per B kpair row (64 + 8 pad)
constexpr int A_STAGE = 64 * A_STR;       // 1280
constexpr int B_STAGE = 16 * B_STR;       // 1152
constexpr int OFF_AH = 0;                      // 2 stages
constexpr int OFF_BH = 2 * A_STAGE;            // 2560
constexpr int OFF_RS = OFF_BH + 2 * B_STAGE;   // 4864  (64*5 floats)
constexpr int OFF_RI = OFF_RS + 320;           // 5184  (64 floats)
constexpr int SMEM_U32 = OFF_RI + 64;          // 5248
constexpr int SMEM_BYTES = SMEM_U32 * 4;       // 20992

DEV_INLINE void mma_bf16(float* c, const unsigned* a, const unsigned* b) {
    asm volatile(
        "mma.sync.aligned.m16n8k16.row.col.f32.bf16.bf16.f32 "
        "{%0,%1,%2,%3}, {%4,%5,%6,%7}, {%8,%9}, {%0,%1,%2,%3};\n"
        : "+f"(c[0]), "+f"(c[1]), "+f"(c[2]), "+f"(c[3])
        : "r"(a[0]), "r"(a[1]), "r"(a[2]), "r"(a[3]), "r"(b[0]), "r"(b[1]));
}

DEV_INLINE void ldsm4(unsigned* r, uint32_t addr) {
    asm volatile(
        "ldmatrix.sync.aligned.m8n8.x4.shared.b16 {%0,%1,%2,%3}, [%4];\n"
        : "=r"(r[0]), "=r"(r[1]), "=r"(r[2]), "=r"(r[3]) : "r"(addr));
}

__global__ void __launch_bounds__(256, 4)
spconv_gemm_kernel(const float* __restrict__ adj, const float* __restrict__ bias,
                   float* __restrict__ out)
{
    extern __shared__ unsigned sm[];
    const uint32_t smb = (uint32_t)__cvta_generic_to_shared(sm);

    const int t    = threadIdx.x;
    const int lane = t & 31, warp = t >> 5;
    const int g = lane >> 2, tg = lane & 3;
    const int wrow = warp >> 1, wcol = warp & 1;     // 4 x 2 warp grid
    const int bx = blockIdx.x, b = blockIdx.y;

    const int lm_row = lane & 15;
    const int lm_kp  = ((lane >> 4) & 1) * 4;

    // A staging: thread row t>>2 (0..63), 32B chunk t&3 -> coalesced
    const int arow = t >> 2, achk = t & 3;
    const float* adj_base =
        adj + ((size_t)(b * Nn) + (size_t)bx * 64 + arow) * Nn + achk * 8;
    // B staging: kpair = t>>4, 4 u32 columns
    const int bkp = t >> 4, bn4 = (t & 15) * 4;
    const unsigned* hpH = g_hpk_hi + (size_t)b * 2048 * 64 + bkp * 64 + bn4;

    float acc[4][4];
#pragma unroll
    for (int nf = 0; nf < 4; nf++)
#pragma unroll
        for (int i = 0; i < 4; i++) acc[nf][i] = 0.f;

    float rsum = 0.f;
    float4 va0, va1;
    uint4 vbh;

    auto ldgA = [&](int kt) {
        va0 = *(const float4*)(adj_base + kt * 32);
        va1 = *(const float4*)(adj_base + kt * 32 + 4);
    };
    auto ldgB = [&](int kt) {
        vbh = *(const uint4*)(hpH + (size_t)kt * 1024);
    };
    auto stsAll = [&](int s) {
        rsum += ((va0.x + va0.y) + (va0.z + va0.w))
              + ((va1.x + va1.y) + (va1.z + va1.w));
        __nv_bfloat162 p0 = __floats2bfloat162_rn(va0.x, va0.y);
        __nv_bfloat162 p1 = __floats2bfloat162_rn(va0.z, va0.w);
        __nv_bfloat162 p2 = __floats2bfloat162_rn(va1.x, va1.y);
        __nv_bfloat162 p3 = __floats2bfloat162_rn(va1.z, va1.w);
        uint4 hv = make_uint4(*reinterpret_cast<unsigned*>(&p0),
                              *reinterpret_cast<unsigned*>(&p1),
                              *reinterpret_cast<unsigned*>(&p2),
                              *reinterpret_cast<unsigned*>(&p3));
        *(uint4*)(sm + OFF_AH + s * A_STAGE + arow * A_STR + achk * 4) = hv;
        *(uint4*)(sm + OFF_BH + s * B_STAGE + bkp * B_STR + bn4) = vbh;
    };
    auto compute = [&](int s) {
        const unsigned* Bh = sm + OFF_BH + s * B_STAGE;
        const uint32_t ahb = smb + (OFF_AH + s * A_STAGE) * 4;
#pragma unroll
        for (int ks = 0; ks < 2; ks++) {
            unsigned bh[4][2];
#pragma unroll
            for (int nf = 0; nf < 4; nf++) {
                int n = wcol * 32 + nf * 8 + g;
                int k0 = (ks * 8 + tg) * B_STR + n;
                bh[nf][0] = Bh[k0];  bh[nf][1] = Bh[k0 + 4 * B_STR];
            }
            unsigned ah[4];
            int aoff = ((wrow * 16 + lm_row) * A_STR + ks * 8 + lm_kp) * 4;
            ldsm4(ah, ahb + aoff);
#pragma unroll
            for (int nf = 0; nf < 4; nf++)
                mma_bf16(acc[nf], ah, bh[nf]);
        }
    };

    // ---- pipeline: one barrier per k-tile ----
    ldgA(0); ldgB(0);
    stsAll(0);
    __syncthreads();
#pragma unroll 1
    for (int kt = 0; kt < 128; kt++) {
        const int cur = kt & 1;
        if (kt < 127) { ldgA(kt + 1); ldgB(kt + 1); }
        compute(cur);
        if (kt < 127) {
            stsAll(1 - cur);
            __syncthreads();
        }
    }
    __syncthreads();

    // ---- rowsum reduce ----
    float* rs   = (float*)(sm + OFF_RS);   // [64][5]
    float* rinv = (float*)(sm + OFF_RI);   // [64]
    rs[arow * 5 + achk] = rsum;
    __syncthreads();
    if (t < 64) {
        float s_ = 1.0f;  // self loop
#pragma unroll
        for (int q = 0; q < 4; q++) s_ += rs[t * 5 + q];
        rinv[t] = 1.0f / s_;
    }
    __syncthreads();

    // ---- epilogue: out = relu((S + h)*rinv) + bias ----
#pragma unroll
    for (int nf = 0; nf < 4; nf++) {
        int r0 = wrow * 16 + g;
        int c  = wcol * 32 + nf * 8 + 2 * tg;
        float ri0 = rinv[r0], ri1 = rinv[r0 + 8];
        int gr0 = bx * 64 + r0;
        size_t o0 = ((size_t)(b * Nn + gr0)) * 64 + c;
        size_t o1 = o0 + (size_t)8 * 64;
        float2 h0 = *(const float2*)(g_h32 + o0);
        float2 h1 = *(const float2*)(g_h32 + o1);
        float bz0 = __ldg(bias + c), bz1 = __ldg(bias + c + 1);
        float2 w0, w1;
        w0.x = fmaxf((acc[nf][0] + h0.x) * ri0, 0.f) + bz0;
        w0.y = fmaxf((acc[nf][1] + h0.y) * ri0, 0.f) + bz1;
        w1.x = fmaxf((acc[nf][2] + h1.x) * ri1, 0.f) + bz0;
        w1.y = fmaxf((acc[nf][3] + h1.y) * ri1, 0.f) + bz1;
        *(float2*)(out + o0) = w0;
        *(float2*)(out + o1) = w1;
    }
}

// ============================================================================
extern "C" void kernel_launch(void* const* d_in, const int* in_sizes, int n_in,
                              void* d_out, int out_size)
{
    const float* x    = (const float*)d_in[0];
    const float* adj  = (const float*)d_in[1];
    const float* wgt  = (const float*)d_in[2];
    const float* bias = (const float*)d_in[3];
    float* out = (float*)d_out;

    spconv_h_kernel<<<dim3(32, 8), 256>>>(x, wgt);
    spconv_gemm_kernel<<<dim3(64, 8), 256, SMEM_BYTES>>>(adj, bias, out);
}

// round 6
// speedup vs baseline: 1.0338x; 1.0338x over previous
#include <cuda_runtime.h>
#include <cuda_bf16.h>
#include <cstdint>

#define DEV_INLINE __device__ __forceinline__

constexpr int Bb = 8;
constexpr int Nn = 4096;

// ---------------- static device scratch (no allocation) ----------------
__device__ float    g_h32[Bb * Nn * 64];          // h fp32 (8 MB)
__device__ unsigned g_hpk_hi[Bb * (Nn/2) * 64];   // h bf16, node-pair packed (4 MB)

// ============================================================================
// Kernel 1: h[b,n,j] = sum_{m,a} x[b,n,m,a]*W[m,p(j),a,w(j)]
// 256 threads: thread = (node pair, p). x loads software-pipelined 1 iter ahead.
// ============================================================================
__global__ void __launch_bounds__(256)
spconv_h_kernel(const float* __restrict__ x, const float* __restrict__ wgt)
{
    __shared__ float ws[128 * 64];   // ws[ka*64 + j],  j = p*16 + w
    const int t = threadIdx.x;
    const int b = blockIdx.y;
    const int ng = t >> 2;                    // 0..63
    const int p  = t & 3;
    const int node0 = blockIdx.x * 128 + ng * 2;

    for (int idx = t; idx < 128 * 64; idx += 256) {
        int ka = idx >> 6, j = idx & 63;
        int m = ka >> 5, a = ka & 31, pp = j >> 4, w = j & 15;
        ws[idx] = wgt[(((m * 4 + pp) * 32 + a) << 4) + w];
    }
    __syncthreads();

    float acc[2][16];
#pragma unroll
    for (int nd = 0; nd < 2; nd++)
#pragma unroll
        for (int i = 0; i < 16; i++) acc[nd][i] = 0.f;

    const float* xr = x + (size_t)(b * Nn + node0) * 128;
    float4 nx0 = *(const float4*)(xr);
    float4 nx1 = *(const float4*)(xr + 128);

#pragma unroll 1
    for (int ka4 = 0; ka4 < 32; ka4++) {
        float4 c0 = nx0, c1 = nx1;
        if (ka4 < 31) {
            nx0 = *(const float4*)(xr + (ka4 + 1) * 4);
            nx1 = *(const float4*)(xr + 128 + (ka4 + 1) * 4);
        }
        float xa[2][4];
        xa[0][0]=c0.x; xa[0][1]=c0.y; xa[0][2]=c0.z; xa[0][3]=c0.w;
        xa[1][0]=c1.x; xa[1][1]=c1.y; xa[1][2]=c1.z; xa[1][3]=c1.w;
#pragma unroll
        for (int i = 0; i < 4; i++) {
            const float4* wr = (const float4*)&ws[(ka4 * 4 + i) * 64 + p * 16];
            float4 w0 = wr[0], w1 = wr[1], w2 = wr[2], w3 = wr[3];
#pragma unroll
            for (int nd = 0; nd < 2; nd++) {
                const float xs = xa[nd][i];
                acc[nd][ 0] = fmaf(xs, w0.x, acc[nd][ 0]);
                acc[nd][ 1] = fmaf(xs, w0.y, acc[nd][ 1]);
                acc[nd][ 2] = fmaf(xs, w0.z, acc[nd][ 2]);
                acc[nd][ 3] = fmaf(xs, w0.w, acc[nd][ 3]);
                acc[nd][ 4] = fmaf(xs, w1.x, acc[nd][ 4]);
                acc[nd][ 5] = fmaf(xs, w1.y, acc[nd][ 5]);
                acc[nd][ 6] = fmaf(xs, w1.z, acc[nd][ 6]);
                acc[nd][ 7] = fmaf(xs, w1.w, acc[nd][ 7]);
                acc[nd][ 8] = fmaf(xs, w2.x, acc[nd][ 8]);
                acc[nd][ 9] = fmaf(xs, w2.y, acc[nd][ 9]);
                acc[nd][10] = fmaf(xs, w2.z, acc[nd][10]);
                acc[nd][11] = fmaf(xs, w2.w, acc[nd][11]);
                acc[nd][12] = fmaf(xs, w3.x, acc[nd][12]);
                acc[nd][13] = fmaf(xs, w3.y, acc[nd][13]);
                acc[nd][14] = fmaf(xs, w3.z, acc[nd][14]);
                acc[nd][15] = fmaf(xs, w3.w, acc[nd][15]);
            }
        }
    }

    // fp32 h for epilogue
#pragma unroll
    for (int nd = 0; nd < 2; nd++) {
        float* hp = g_h32 + (size_t)(b * Nn + node0 + nd) * 64 + p * 16;
#pragma unroll
        for (int w4 = 0; w4 < 4; w4++)
            *(float4*)(hp + w4 * 4) = make_float4(acc[nd][w4*4+0], acc[nd][w4*4+1],
                                                  acc[nd][w4*4+2], acc[nd][w4*4+3]);
    }

    // node-pair packed bf16 (pair is thread-local)
    {
        const size_t pb = ((size_t)(b * 2048 + (node0 >> 1))) * 64 + p * 16;
        unsigned hi[16];
#pragma unroll
        for (int w = 0; w < 16; w++) {
            __nv_bfloat162 t2 = __floats2bfloat162_rn(acc[0][w], acc[1][w]);
            hi[w] = *reinterpret_cast<unsigned*>(&t2);
        }
#pragma unroll
        for (int w4 = 0; w4 < 4; w4++)
            *(uint4*)(g_hpk_hi + pb + w4 * 4) =
                make_uint4(hi[w4*4], hi[w4*4+1], hi[w4*4+2], hi[w4*4+3]);
    }
}

// ============================================================================
// Kernel 2: per-batch C = adj @ h, fused rowsum/normalize/self-loop/relu/bias.
// cp.async 3-stage pipeline; A staged as fp32 (stride 40), fragments built by
// LDS.64 + bf16 pack; rowsum accumulated from fragment loads (wcol==0 warps).
// BM=64 BN=64 BK=32, 256 thr, warp tile 16x32, 4 CTAs/SM.
// ============================================================================
constexpr int A_ROWSTR = 40;                   // floats per A row (32 + 8 pad)
constexpr int A_STAGE  = 64 * A_ROWSTR;        // 2560 u32
constexpr int B_STR    = 72;                   // u32 per B kpair row
constexpr int B_STAGE  = 16 * B_STR;           // 1152 u32
constexpr int STAGES   = 3;
constexpr int OFF_A  = 0;
constexpr int OFF_B  = STAGES * A_STAGE;              // 7680
constexpr int OFF_RS = OFF_B + STAGES * B_STAGE;      // 11136 (64 floats)
constexpr int OFF_RI = OFF_RS + 64;                   // 11200 (64 floats)
constexpr int SMEM_U32 = OFF_RI + 64;                 // 11264
constexpr int SMEM_BYTES = SMEM_U32 * 4;              // 45056 (< 48K default)

DEV_INLINE void mma_bf16(float* c, const unsigned* a, const unsigned* b) {
    asm volatile(
        "mma.sync.aligned.m16n8k16.row.col.f32.bf16.bf16.f32 "
        "{%0,%1,%2,%3}, {%4,%5,%6,%7}, {%8,%9}, {%0,%1,%2,%3};\n"
        : "+f"(c[0]), "+f"(c[1]), "+f"(c[2]), "+f"(c[3])
        : "r"(a[0]), "r"(a[1]), "r"(a[2]), "r"(a[3]), "r"(b[0]), "r"(b[1]));
}

DEV_INLINE void cp16(uint32_t saddr, const void* gptr) {
    asm volatile("cp.async.cg.shared.global [%0], [%1], 16;\n"
                 :: "r"(saddr), "l"(gptr));
}
DEV_INLINE void cp_commit() { asm volatile("cp.async.commit_group;\n"); }
DEV_INLINE void cp_wait1()  { asm volatile("cp.async.wait_group 1;\n"); }
DEV_INLINE void cp_wait0()  { asm volatile("cp.async.wait_group 0;\n"); }

DEV_INLINE unsigned packbf(float2 v) {
    __nv_bfloat162 t2 = __floats2bfloat162_rn(v.x, v.y);
    return *reinterpret_cast<unsigned*>(&t2);
}

__global__ void __launch_bounds__(256, 4)
spconv_gemm_kernel(const float* __restrict__ adj, const float* __restrict__ bias,
                   float* __restrict__ out)
{
    extern __shared__ unsigned sm[];
    const uint32_t smb = (uint32_t)__cvta_generic_to_shared(sm);

    const int t    = threadIdx.x;
    const int lane = t & 31, warp = t >> 5;
    const int g = lane >> 2, tg = lane & 3;
    const int wrow = warp >> 1, wcol = warp & 1;     // 4 x 2 warp grid
    const int bx = blockIdx.x, b = blockIdx.y;

    // A copy: thread row t>>2 (0..63), 32B chunk t&3 (coalesced)
    const int arow = t >> 2, achk = t & 3;
    const float* adj_base =
        adj + ((size_t)(b * Nn) + (size_t)bx * 64 + arow) * Nn + achk * 8;
    const uint32_t sa_base = smb + (OFF_A + arow * A_ROWSTR + achk * 8) * 4;
    // B copy: kpair = t>>4, 4 u32 columns
    const int bkp = t >> 4, bn4 = (t & 15) * 4;
    const unsigned* hpH = g_hpk_hi + (size_t)b * 2048 * 64 + bkp * 64 + bn4;
    const uint32_t sb_base = smb + (OFF_B + bkp * B_STR + bn4) * 4;

    float acc[4][4];
#pragma unroll
    for (int nf = 0; nf < 4; nf++)
#pragma unroll
        for (int i = 0; i < 4; i++) acc[nf][i] = 0.f;

    float rsum0 = 0.f, rsum1 = 0.f;
    const int r0 = wrow * 16 + g;     // fragment rows r0, r0+8

    auto issue = [&](int kt, int s) {
        const float* ga = adj_base + (size_t)kt * 32;
        uint32_t sa = sa_base + s * (A_STAGE * 4);
        cp16(sa,      ga);
        cp16(sa + 16, ga + 4);
        cp16(sb_base + s * (B_STAGE * 4), hpH + (size_t)kt * 1024);
        cp_commit();
    };

    auto compute = [&](int s) {
        const float*    Af = (const float*)(sm + OFF_A + s * A_STAGE);
        const unsigned* Bh = sm + OFF_B + s * B_STAGE;
#pragma unroll
        for (int ks = 0; ks < 2; ks++) {
            unsigned bh[4][2];
#pragma unroll
            for (int nf = 0; nf < 4; nf++) {
                int n = wcol * 32 + nf * 8 + g;
                int k0 = (ks * 8 + tg) * B_STR + n;
                bh[nf][0] = Bh[k0];  bh[nf][1] = Bh[k0 + 4 * B_STR];
            }
            const int kb = ks * 16 + 2 * tg;
            float2 p0 = *(const float2*)(Af + (r0    ) * A_ROWSTR + kb);
            float2 p1 = *(const float2*)(Af + (r0 + 8) * A_ROWSTR + kb);
            float2 p2 = *(const float2*)(Af + (r0    ) * A_ROWSTR + kb + 8);
            float2 p3 = *(const float2*)(Af + (r0 + 8) * A_ROWSTR + kb + 8);
            if (wcol == 0) {
                rsum0 += (p0.x + p0.y) + (p2.x + p2.y);
                rsum1 += (p1.x + p1.y) + (p3.x + p3.y);
            }
            unsigned ah[4];
            ah[0] = packbf(p0); ah[1] = packbf(p1);
            ah[2] = packbf(p2); ah[3] = packbf(p3);
#pragma unroll
            for (int nf = 0; nf < 4; nf++)
                mma_bf16(acc[nf], ah, bh[nf]);
        }
    };

    // ---- 3-stage pipeline ----
    issue(0, 0);
    issue(1, 1);
    int s = 0, si = 2;
#pragma unroll 1
    for (int kt = 0; kt < 128; kt++) {
        if (kt == 127) cp_wait0(); else cp_wait1();
        __syncthreads();
        compute(s);
        if (kt + 2 < 128) issue(kt + 2, si);
        s  = (s  == 2) ? 0 : s + 1;
        si = (si == 2) ? 0 : si + 1;
        // barrier before the slot being written next iter is recycled is the
        // wait+sync at the top of the next iteration
        __syncthreads();
    }

    // ---- rowsum -> rinv ----
    float* rs   = (float*)(sm + OFF_RS);   // [64]
    float* rinv = (float*)(sm + OFF_RI);   // [64]
    if (wcol == 0) {
        rsum0 += __shfl_xor_sync(0xffffffffu, rsum0, 1);
        rsum0 += __shfl_xor_sync(0xffffffffu, rsum0, 2);
        rsum1 += __shfl_xor_sync(0xffffffffu, rsum1, 1);
        rsum1 += __shfl_xor_sync(0xffffffffu, rsum1, 2);
        if (tg == 0) { rs[r0] = rsum0; rs[r0 + 8] = rsum1; }
    }
    __syncthreads();
    if (t < 64) rinv[t] = 1.0f / (1.0f + rs[t]);   // +1 = self loop
    __syncthreads();

    // ---- epilogue: out = relu((S + h)*rinv) + bias ----
#pragma unroll
    for (int nf = 0; nf < 4; nf++) {
        int c  = wcol * 32 + nf * 8 + 2 * tg;
        float ri0 = rinv[r0], ri1 = rinv[r0 + 8];
        int gr0 = bx * 64 + r0;
        size_t o0 = ((size_t)(b * Nn + gr0)) * 64 + c;
        size_t o1 = o0 + (size_t)8 * 64;
        float2 h0 = *(const float2*)(g_h32 + o0);
        float2 h1 = *(const float2*)(g_h32 + o1);
        float bz0 = __ldg(bias + c), bz1 = __ldg(bias + c + 1);
        float2 w0, w1;
        w0.x = fmaxf((acc[nf][0] + h0.x) * ri0, 0.f) + bz0;
        w0.y = fmaxf((acc[nf][1] + h0.y) * ri0, 0.f) + bz1;
        w1.x = fmaxf((acc[nf][2] + h1.x) * ri1, 0.f) + bz0;
        w1.y = fmaxf((acc[nf][3] + h1.y) * ri1, 0.f) + bz1;
        *(float2*)(out + o0) = w0;
        *(float2*)(out + o1) = w1;
    }
}

// ============================================================================
extern "C" void kernel_launch(void* const* d_in, const int* in_sizes, int n_in,
                              void* d_out, int out_size)
{
    const float* x    = (const float*)d_in[0];
    const float* adj  = (const float*)d_in[1];
    const float* wgt  = (const float*)d_in[2];
    const float* bias = (const float*)d_in[3];
    float* out = (float*)d_out;

    spconv_h_kernel<<<dim3(32, 8), 256>>>(x, wgt);
    spconv_gemm_kernel<<<dim3(64, 8), 256, SMEM_BYTES>>>(adj, bias, out);
}

// round 7
// speedup vs baseline: 1.1171x; 1.0806x over previous
#include <cuda_runtime.h>
#include <cuda_bf16.h>
#include <cstdint>

#define DEV_INLINE __device__ __forceinline__

constexpr int Bb = 8;
constexpr int Nn = 4096;

// ---------------- static device scratch (no allocation) ----------------
__device__ float    g_h32[Bb * Nn * 64];          // h fp32 (8 MB)
__device__ unsigned g_hpk_hi[Bb * (Nn/2) * 64];   // h bf16, node-pair packed (4 MB)

// ============================================================================
// Kernel 1: h[b,n,j] = sum_{m,a} x[b,n,m,a]*W[m,p(j),a,w(j)]
// 128 threads: thread = (4-node group, p). W-LDS amortized over 4 nodes;
// x loads prefetched one ka4-iteration ahead; pair packing thread-local.
// ============================================================================
__global__ void __launch_bounds__(128)
spconv_h_kernel(const float* __restrict__ x, const float* __restrict__ wgt)
{
    __shared__ float ws[128 * 64];   // ws[ka*64 + j],  j = p*16 + w
    const int t = threadIdx.x;
    const int b = blockIdx.y;
    const int ng = t >> 2;                    // 0..31
    const int p  = t & 3;
    const int node0 = blockIdx.x * 128 + ng * 4;

    for (int idx = t; idx < 128 * 64; idx += 128) {
        int ka = idx >> 6, j = idx & 63;
        int m = ka >> 5, a = ka & 31, pp = j >> 4, w = j & 15;
        ws[idx] = wgt[(((m * 4 + pp) * 32 + a) << 4) + w];
    }
    __syncthreads();

    float acc[4][16];
#pragma unroll
    for (int nd = 0; nd < 4; nd++)
#pragma unroll
        for (int i = 0; i < 16; i++) acc[nd][i] = 0.f;

    const float* xr = x + (size_t)(b * Nn + node0) * 128;
    float4 nxt[4];
#pragma unroll
    for (int nd = 0; nd < 4; nd++) nxt[nd] = *(const float4*)(xr + nd * 128);

#pragma unroll 1
    for (int ka4 = 0; ka4 < 32; ka4++) {
        float4 cur[4];
#pragma unroll
        for (int nd = 0; nd < 4; nd++) cur[nd] = nxt[nd];
        if (ka4 < 31) {
#pragma unroll
            for (int nd = 0; nd < 4; nd++)
                nxt[nd] = *(const float4*)(xr + nd * 128 + (ka4 + 1) * 4);
        }
        float xa[4][4];
#pragma unroll
        for (int nd = 0; nd < 4; nd++) {
            xa[nd][0]=cur[nd].x; xa[nd][1]=cur[nd].y;
            xa[nd][2]=cur[nd].z; xa[nd][3]=cur[nd].w;
        }
#pragma unroll
        for (int i = 0; i < 4; i++) {
            const float4* wr = (const float4*)&ws[(ka4 * 4 + i) * 64 + p * 16];
            float4 w0 = wr[0], w1 = wr[1], w2 = wr[2], w3 = wr[3];
#pragma unroll
            for (int nd = 0; nd < 4; nd++) {
                const float xs = xa[nd][i];
                acc[nd][ 0] = fmaf(xs, w0.x, acc[nd][ 0]);
                acc[nd][ 1] = fmaf(xs, w0.y, acc[nd][ 1]);
                acc[nd][ 2] = fmaf(xs, w0.z, acc[nd][ 2]);
                acc[nd][ 3] = fmaf(xs, w0.w, acc[nd][ 3]);
                acc[nd][ 4] = fmaf(xs, w1.x, acc[nd][ 4]);
                acc[nd][ 5] = fmaf(xs, w1.y, acc[nd][ 5]);
                acc[nd][ 6] = fmaf(xs, w1.z, acc[nd][ 6]);
                acc[nd][ 7] = fmaf(xs, w1.w, acc[nd][ 7]);
                acc[nd][ 8] = fmaf(xs, w2.x, acc[nd][ 8]);
                acc[nd][ 9] = fmaf(xs, w2.y, acc[nd][ 9]);
                acc[nd][10] = fmaf(xs, w2.z, acc[nd][10]);
                acc[nd][11] = fmaf(xs, w2.w, acc[nd][11]);
                acc[nd][12] = fmaf(xs, w3.x, acc[nd][12]);
                acc[nd][13] = fmaf(xs, w3.y, acc[nd][13]);
                acc[nd][14] = fmaf(xs, w3.z, acc[nd][14]);
                acc[nd][15] = fmaf(xs, w3.w, acc[nd][15]);
            }
        }
    }

    // fp32 h for epilogue
#pragma unroll
    for (int nd = 0; nd < 4; nd++) {
        float* hp = g_h32 + (size_t)(b * Nn + node0 + nd) * 64 + p * 16;
#pragma unroll
        for (int w4 = 0; w4 < 4; w4++)
            *(float4*)(hp + w4 * 4) = make_float4(acc[nd][w4*4+0], acc[nd][w4*4+1],
                                                  acc[nd][w4*4+2], acc[nd][w4*4+3]);
    }

    // node-pair packed bf16 (pairs thread-local)
#pragma unroll
    for (int pr = 0; pr < 2; pr++) {
        const size_t pb = ((size_t)(b * 2048 + (node0 >> 1) + pr)) * 64 + p * 16;
        unsigned hi[16];
#pragma unroll
        for (int w = 0; w < 16; w++) {
            __nv_bfloat162 t2 = __floats2bfloat162_rn(acc[pr*2+0][w], acc[pr*2+1][w]);
            hi[w] = *reinterpret_cast<unsigned*>(&t2);
        }
#pragma unroll
        for (int w4 = 0; w4 < 4; w4++)
            *(uint4*)(g_hpk_hi + pb + w4 * 4) =
                make_uint4(hi[w4*4], hi[w4*4+1], hi[w4*4+2], hi[w4*4+3]);
    }
}

// ============================================================================
// Kernel 2: per-batch C = adj @ h, fused rowsum/normalize/self-loop/relu/bias.
// cp.async 4-stage pipeline, ONE barrier per k-tile (wait->sync->compute->issue).
// A staged fp32 (stride 40), fragments via LDS.64 + bf16 pack; rowsum from
// fragment loads. BM=64 BN=64 BK=32, 256 thr, warp tile 16x32, 3 CTAs/SM.
// ============================================================================
constexpr int A_ROWSTR = 40;                   // floats per A row (32 + 8 pad)
constexpr int A_STAGE  = 64 * A_ROWSTR;        // 2560 u32
constexpr int B_STR    = 72;                   // u32 per B kpair row
constexpr int B_STAGE  = 16 * B_STR;           // 1152 u32
constexpr int STAGES   = 4;
constexpr int OFF_A  = 0;
constexpr int OFF_B  = STAGES * A_STAGE;              // 10240
constexpr int OFF_RS = OFF_B + STAGES * B_STAGE;      // 14848 (64 floats)
constexpr int OFF_RI = OFF_RS + 64;                   // 14912 (64 floats)
constexpr int SMEM_U32 = OFF_RI + 64;                 // 14976
constexpr int SMEM_BYTES = SMEM_U32 * 4;              // 59904

DEV_INLINE void mma_bf16(float* c, const unsigned* a, const unsigned* b) {
    asm volatile(
        "mma.sync.aligned.m16n8k16.row.col.f32.bf16.bf16.f32 "
        "{%0,%1,%2,%3}, {%4,%5,%6,%7}, {%8,%9}, {%0,%1,%2,%3};\n"
        : "+f"(c[0]), "+f"(c[1]), "+f"(c[2]), "+f"(c[3])
        : "r"(a[0]), "r"(a[1]), "r"(a[2]), "r"(a[3]), "r"(b[0]), "r"(b[1]));
}

DEV_INLINE void cp16(uint32_t saddr, const void* gptr) {
    asm volatile("cp.async.cg.shared.global [%0], [%1], 16;\n"
                 :: "r"(saddr), "l"(gptr));
}
DEV_INLINE void cp_commit() { asm volatile("cp.async.commit_group;\n"); }
DEV_INLINE void cp_wait2()  { asm volatile("cp.async.wait_group 2;\n"); }
DEV_INLINE void cp_wait0()  { asm volatile("cp.async.wait_group 0;\n"); }

DEV_INLINE unsigned packbf(float2 v) {
    __nv_bfloat162 t2 = __floats2bfloat162_rn(v.x, v.y);
    return *reinterpret_cast<unsigned*>(&t2);
}

__global__ void __launch_bounds__(256, 3)
spconv_gemm_kernel(const float* __restrict__ adj, const float* __restrict__ bias,
                   float* __restrict__ out)
{
    extern __shared__ unsigned sm[];
    const uint32_t smb = (uint32_t)__cvta_generic_to_shared(sm);

    const int t    = threadIdx.x;
    const int lane = t & 31, warp = t >> 5;
    const int g = lane >> 2, tg = lane & 3;
    const int wrow = warp >> 1, wcol = warp & 1;     // 4 x 2 warp grid
    const int bx = blockIdx.x, b = blockIdx.y;

    // A copy: thread row t>>2 (0..63), 32B chunk t&3 (coalesced)
    const int arow = t >> 2, achk = t & 3;
    const float* adj_base =
        adj + ((size_t)(b * Nn) + (size_t)bx * 64 + arow) * Nn + achk * 8;
    const uint32_t sa_base = smb + (OFF_A + arow * A_ROWSTR + achk * 8) * 4;
    // B copy: kpair = t>>4, 4 u32 columns
    const int bkp = t >> 4, bn4 = (t & 15) * 4;
    const unsigned* hpH = g_hpk_hi + (size_t)b * 2048 * 64 + bkp * 64 + bn4;
    const uint32_t sb_base = smb + (OFF_B + bkp * B_STR + bn4) * 4;

    float acc[4][4];
#pragma unroll
    for (int nf = 0; nf < 4; nf++)
#pragma unroll
        for (int i = 0; i < 4; i++) acc[nf][i] = 0.f;

    float rsum0 = 0.f, rsum1 = 0.f;
    const int r0 = wrow * 16 + g;     // fragment rows r0, r0+8

    auto issue = [&](int kt, int s) {
        const float* ga = adj_base + (size_t)kt * 32;
        uint32_t sa = sa_base + s * (A_STAGE * 4);
        cp16(sa,      ga);
        cp16(sa + 16, ga + 4);
        cp16(sb_base + s * (B_STAGE * 4), hpH + (size_t)kt * 1024);
        cp_commit();
    };

    auto compute = [&](int s) {
        const float*    Af = (const float*)(sm + OFF_A + s * A_STAGE);
        const unsigned* Bh = sm + OFF_B + s * B_STAGE;
#pragma unroll
        for (int ks = 0; ks < 2; ks++) {
            unsigned bh[4][2];
#pragma unroll
            for (int nf = 0; nf < 4; nf++) {
                int n = wcol * 32 + nf * 8 + g;
                int k0 = (ks * 8 + tg) * B_STR + n;
                bh[nf][0] = Bh[k0];  bh[nf][1] = Bh[k0 + 4 * B_STR];
            }
            const int kb = ks * 16 + 2 * tg;
            float2 p0 = *(const float2*)(Af + (r0    ) * A_ROWSTR + kb);
            float2 p1 = *(const float2*)(Af + (r0 + 8) * A_ROWSTR + kb);
            float2 p2 = *(const float2*)(Af + (r0    ) * A_ROWSTR + kb + 8);
            float2 p3 = *(const float2*)(Af + (r0 + 8) * A_ROWSTR + kb + 8);
            if (wcol == 0) {
                rsum0 += (p0.x + p0.y) + (p2.x + p2.y);
                rsum1 += (p1.x + p1.y) + (p3.x + p3.y);
            }
            unsigned ah[4];
            ah[0] = packbf(p0); ah[1] = packbf(p1);
            ah[2] = packbf(p2); ah[3] = packbf(p3);
#pragma unroll
            for (int nf = 0; nf < 4; nf++)
                mma_bf16(acc[nf], ah, bh[nf]);
        }
    };

    // ---- 4-stage pipeline, one barrier per tile ----
    issue(0, 0);
    issue(1, 1);
    issue(2, 2);
    int s = 0, si = 3;
#pragma unroll 1
    for (int kt = 0; kt < 128; kt++) {
        if (kt >= 125) cp_wait0(); else cp_wait2();
        __syncthreads();
        compute(s);
        if (kt + 3 < 128) issue(kt + 3, si);
        else cp_commit();                    // keep group count semantics in tail
        s  = (s  == STAGES - 1) ? 0 : s + 1;
        si = (si == STAGES - 1) ? 0 : si + 1;
    }

    // ---- rowsum -> rinv ----
    float* rs   = (float*)(sm + OFF_RS);   // [64]
    float* rinv = (float*)(sm + OFF_RI);   // [64]
    __syncthreads();
    if (wcol == 0) {
        rsum0 += __shfl_xor_sync(0xffffffffu, rsum0, 1);
        rsum0 += __shfl_xor_sync(0xffffffffu, rsum0, 2);
        rsum1 += __shfl_xor_sync(0xffffffffu, rsum1, 1);
        rsum1 += __shfl_xor_sync(0xffffffffu, rsum1, 2);
        if (tg == 0) { rs[r0] = rsum0; rs[r0 + 8] = rsum1; }
    }
    __syncthreads();
    if (t < 64) rinv[t] = 1.0f / (1.0f + rs[t]);   // +1 = self loop
    __syncthreads();

    // ---- epilogue: out = relu((S + h)*rinv) + bias ----
#pragma unroll
    for (int nf = 0; nf < 4; nf++) {
        int c  = wcol * 32 + nf * 8 + 2 * tg;
        float ri0 = rinv[r0], ri1 = rinv[r0 + 8];
        int gr0 = bx * 64 + r0;
        size_t o0 = ((size_t)(b * Nn + gr0)) * 64 + c;
        size_t o1 = o0 + (size_t)8 * 64;
        float2 h0 = *(const float2*)(g_h32 + o0);
        float2 h1 = *(const float2*)(g_h32 + o1);
        float bz0 = __ldg(bias + c), bz1 = __ldg(bias + c + 1);
        float2 w0, w1;
        w0.x = fmaxf((acc[nf][0] + h0.x) * ri0, 0.f) + bz0;
        w0.y = fmaxf((acc[nf][1] + h0.y) * ri0, 0.f) + bz1;
        w1.x = fmaxf((acc[nf][2] + h1.x) * ri1, 0.f) + bz0;
        w1.y = fmaxf((acc[nf][3] + h1.y) * ri1, 0.f) + bz1;
        *(float2*)(out + o0) = w0;
        *(float2*)(out + o1) = w1;
    }
}

// ============================================================================
extern "C" void kernel_launch(void* const* d_in, const int* in_sizes, int n_in,
                              void* d_out, int out_size)
{
    const float* x    = (const float*)d_in[0];
    const float* adj  = (const float*)d_in[1];
    const float* wgt  = (const float*)d_in[2];
    const float* bias = (const float*)d_in[3];
    float* out = (float*)d_out;

    cudaFuncSetAttribute(spconv_gemm_kernel,
                         cudaFuncAttributeMaxDynamicSharedMemorySize, SMEM_BYTES);

    spconv_h_kernel<<<dim3(32, 8), 128>>>(x, wgt);
    spconv_gemm_kernel<<<dim3(64, 8), 256, SMEM_BYTES>>>(adj, bias, out);
}